// round 2
// baseline (speedup 1.0000x reference)
#include <cuda_runtime.h>
#include <math.h>

// Problem constants (RouterLinear): B=1024, IN=4096, OUT=4096, K=64, TOPK=64
constexpr int Bb   = 1024;
constexpr int IN_  = 4096;
constexpr int OUT_ = 4096;
constexpr int Kf   = 64;
constexpr int TOPK = 64;

// Scratch (device globals — no allocation allowed in kernel_launch)
__device__ float g_S[Bb * IN_];     // dense scattered x: 16 MB
__device__ float g_res[Bb * OUT_];  // GEMM result: 16 MB

// ---------------------------------------------------------------------------
// Kernel 1: zero S
// ---------------------------------------------------------------------------
__global__ void zero_S_kernel() {
    int t = blockIdx.x * blockDim.x + threadIdx.x;
    float4* p = reinterpret_cast<float4*>(g_S);
    // Bb*IN_/4 float4 elements = 4,194,304
    if (t < (Bb * IN_ / 4)) p[t] = make_float4(0.f, 0.f, 0.f, 0.f);
}

// ---------------------------------------------------------------------------
// Kernel 2: scatter x into S. One thread per sample row -> fully deterministic
// (duplicate indices accumulate in k-order, matching the reference einsum sum
// over k; no atomics so replays are bit-identical).
// ---------------------------------------------------------------------------
__global__ void scatter_kernel(const float* __restrict__ x,
                               const int* __restrict__ prev_idx) {
    int b = blockIdx.x * blockDim.x + threadIdx.x;
    if (b >= Bb) return;
    const float* xr  = x + b * Kf;
    const int*   ir  = prev_idx + b * Kf;
    float* Srow = g_S + (size_t)b * IN_;
    #pragma unroll 8
    for (int k = 0; k < Kf; k++) {
        Srow[ir[k]] += xr[k];
    }
}

// ---------------------------------------------------------------------------
// Kernel 3: SGEMM  g_res[m,n] = sum_i g_S[m,i] * W[n,i] + bias[n]
// Both operands are contiguous along i (NT-style). Classic 128x128x8 tiling,
// 256 threads, 8x8 microtile per thread.
// ---------------------------------------------------------------------------
constexpr int BM = 128, BN = 128, BK = 8, TM = 8, TN = 8;

__global__ __launch_bounds__(256, 2) void gemm_kernel(
    const float* __restrict__ W, const float* __restrict__ bias) {
    __shared__ float As[BK][BM];
    __shared__ float Bs[BK][BN];

    const int tid = threadIdx.x;
    const int m0 = blockIdx.y * BM;
    const int n0 = blockIdx.x * BN;

    // load mapping: 256 threads load 128 rows x 8 cols as float4
    const int lr = tid >> 1;          // 0..127
    const int lc = (tid & 1) * 4;     // 0 or 4

    const int tm = tid >> 4;          // 0..15
    const int tn = tid & 15;          // 0..15

    const float* Arow = g_S + (size_t)(m0 + lr) * IN_ + lc;
    const float* Brow = W   + (size_t)(n0 + lr) * IN_ + lc;

    float acc[TM][TN];
    #pragma unroll
    for (int m = 0; m < TM; m++)
        #pragma unroll
        for (int n = 0; n < TN; n++) acc[m][n] = 0.f;

    for (int i0 = 0; i0 < IN_; i0 += BK) {
        float4 av = *reinterpret_cast<const float4*>(Arow + i0);
        float4 bv = *reinterpret_cast<const float4*>(Brow + i0);
        As[lc + 0][lr] = av.x; As[lc + 1][lr] = av.y;
        As[lc + 2][lr] = av.z; As[lc + 3][lr] = av.w;
        Bs[lc + 0][lr] = bv.x; Bs[lc + 1][lr] = bv.y;
        Bs[lc + 2][lr] = bv.z; Bs[lc + 3][lr] = bv.w;
        __syncthreads();

        #pragma unroll
        for (int kk = 0; kk < BK; kk++) {
            float ra[TM], rb[TN];
            #pragma unroll
            for (int m = 0; m < TM; m++) ra[m] = As[kk][tm * TM + m];
            #pragma unroll
            for (int n = 0; n < TN; n++) rb[n] = Bs[kk][tn * TN + n];
            #pragma unroll
            for (int m = 0; m < TM; m++)
                #pragma unroll
                for (int n = 0; n < TN; n++)
                    acc[m][n] = fmaf(ra[m], rb[n], acc[m][n]);
        }
        __syncthreads();
    }

    // epilogue: add bias, write to g_res
    float bv[TN];
    #pragma unroll
    for (int n = 0; n < TN; n++) bv[n] = bias[n0 + tn * TN + n];

    #pragma unroll
    for (int m = 0; m < TM; m++) {
        float* orow = g_res + (size_t)(m0 + tm * TM + m) * OUT_ + n0 + tn * TN;
        #pragma unroll
        for (int n = 0; n < TN; n++) orow[n] = acc[m][n] + bv[n];
    }
}

// ---------------------------------------------------------------------------
// Kernel 4: per-row top-64 (sorted desc, ties -> lower index, matching
// jax.lax.top_k). Iterative argmax over a shared-memory copy of the row.
// ---------------------------------------------------------------------------
__global__ __launch_bounds__(256) void topk_kernel(float* __restrict__ out,
                                                   int out_size) {
    __shared__ float sval[OUT_];
    __shared__ float rv[256];
    __shared__ int   ri[256];

    const int b = blockIdx.x;
    const int tid = threadIdx.x;
    const float* row = g_res + (size_t)b * OUT_;

    for (int j = tid; j < OUT_; j += 256) sval[j] = row[j];
    __syncthreads();

    const bool write_idx = (out_size >= 2 * Bb * TOPK);

    for (int t = 0; t < TOPK; t++) {
        float v = -INFINITY;
        int   bi = OUT_;
        for (int j = tid; j < OUT_; j += 256) {
            float s = sval[j];
            if (s > v) { v = s; bi = j; }  // strided j increases -> in-thread ties keep lowest j
        }
        rv[tid] = v; ri[tid] = bi;
        __syncthreads();
        #pragma unroll
        for (int s = 128; s > 0; s >>= 1) {
            if (tid < s) {
                float ov = rv[tid + s]; int oi = ri[tid + s];
                if (ov > rv[tid] || (ov == rv[tid] && oi < ri[tid])) {
                    rv[tid] = ov; ri[tid] = oi;
                }
            }
            __syncthreads();
        }
        if (tid == 0) {
            out[b * TOPK + t] = rv[0];
            if (write_idx) out[Bb * TOPK + b * TOPK + t] = (float)ri[0];
            sval[ri[0]] = -INFINITY;
        }
        __syncthreads();
    }
}

// ---------------------------------------------------------------------------
// Launch: inputs in metadata order: x, weight, bias, prev_idx, (top_k)
// ---------------------------------------------------------------------------
extern "C" void kernel_launch(void* const* d_in, const int* in_sizes, int n_in,
                              void* d_out, int out_size) {
    const float* x        = (const float*)d_in[0];
    const float* weight   = (const float*)d_in[1];
    const float* bias     = (const float*)d_in[2];
    const int*   prev_idx = (const int*)d_in[3];
    float* out = (float*)d_out;

    // 1) zero S
    {
        int n4 = Bb * IN_ / 4;
        zero_S_kernel<<<(n4 + 255) / 256, 256>>>();
    }
    // 2) scatter x into S (deterministic, per-row serial)
    scatter_kernel<<<(Bb + 255) / 256, 256>>>(x, prev_idx);
    // 3) GEMM + bias
    {
        dim3 grid(OUT_ / BN, Bb / BM);
        gemm_kernel<<<grid, 256>>>(weight, bias);
    }
    // 4) top-k
    topk_kernel<<<Bb, 256>>>(out, out_size);
}

// round 4
// speedup vs baseline: 5.8276x; 5.8276x over previous
#include <cuda_runtime.h>
#include <math.h>

// RouterLinear: B=1024, IN=4096, OUT=4096, K=64, TOPK=64
constexpr int Bb   = 1024;
constexpr int IN_  = 4096;
constexpr int OUT_ = 4096;
constexpr int Kf   = 64;
constexpr int TOPK = 64;

// Scratch: transposed weight WT[i][o] = W[o][i]  (64 MB, L2-resident)
__device__ float g_WT[(size_t)IN_ * OUT_];

// ---------------------------------------------------------------------------
// Kernel 1: tiled transpose W[OUT][IN] -> WT[IN][OUT]
// ---------------------------------------------------------------------------
__global__ __launch_bounds__(256) void transpose_kernel(const float* __restrict__ W) {
    __shared__ float tile[32][33];
    const int tx = threadIdx.x;          // 0..31
    const int ty = threadIdx.y;          // 0..7
    const int x0 = blockIdx.x * 32;      // column (IN) tile base
    const int y0 = blockIdx.y * 32;      // row (OUT) tile base

    #pragma unroll
    for (int i = 0; i < 32; i += 8)
        tile[ty + i][tx] = W[(size_t)(y0 + ty + i) * IN_ + (x0 + tx)];
    __syncthreads();
    #pragma unroll
    for (int i = 0; i < 32; i += 8)
        g_WT[(size_t)(x0 + ty + i) * OUT_ + (y0 + tx)] = tile[tx][ty + i];
}

// ---------------------------------------------------------------------------
// Kernel 2: fused gather-matvec + bias + top-64.
// One block per batch row. 512 threads x 8 output columns each.
// Thread t owns columns [4t, 4t+3] and [2048+4t, 2048+4t+3].
// ---------------------------------------------------------------------------
__global__ __launch_bounds__(512) void router_topk_kernel(
    const float* __restrict__ x, const int* __restrict__ prev_idx,
    const float* __restrict__ bias, float* __restrict__ out, int out_size) {

    __shared__ float s_x[Kf];
    __shared__ int   s_i[Kf];
    __shared__ float s_wv[16];
    __shared__ int   s_wi[16];
    __shared__ int   s_bi;  // broadcast winner index

    const int b    = blockIdx.x;
    const int tid  = threadIdx.x;
    const int lane = tid & 31;
    const int wid  = tid >> 5;

    if (tid < Kf) {
        s_x[tid] = x[b * Kf + tid];
        s_i[tid] = prev_idx[b * Kf + tid];
    }
    __syncthreads();

    const int c0 = tid * 4;
    const int c1 = 2048 + tid * 4;

    float4 a0 = make_float4(0.f, 0.f, 0.f, 0.f);
    float4 a1 = make_float4(0.f, 0.f, 0.f, 0.f);

    #pragma unroll 4
    for (int k = 0; k < Kf; k++) {
        const float* row = g_WT + (size_t)s_i[k] * OUT_;
        const float  xv  = s_x[k];
        float4 w0 = *reinterpret_cast<const float4*>(row + c0);
        float4 w1 = *reinterpret_cast<const float4*>(row + c1);
        a0.x = fmaf(w0.x, xv, a0.x); a0.y = fmaf(w0.y, xv, a0.y);
        a0.z = fmaf(w0.z, xv, a0.z); a0.w = fmaf(w0.w, xv, a0.w);
        a1.x = fmaf(w1.x, xv, a1.x); a1.y = fmaf(w1.y, xv, a1.y);
        a1.z = fmaf(w1.z, xv, a1.z); a1.w = fmaf(w1.w, xv, a1.w);
    }

    // bias
    {
        float4 b0 = *reinterpret_cast<const float4*>(bias + c0);
        float4 b1 = *reinterpret_cast<const float4*>(bias + c1);
        a0.x += b0.x; a0.y += b0.y; a0.z += b0.z; a0.w += b0.w;
        a1.x += b1.x; a1.y += b1.y; a1.z += b1.z; a1.w += b1.w;
    }

    // register-resident values, ascending-column order (tie -> lowest index)
    float v[8] = {a0.x, a0.y, a0.z, a0.w, a1.x, a1.y, a1.z, a1.w};

    // cached per-thread local argmax (strict > keeps lowest column on ties)
    float lm = v[0]; int lj = 0;
    #pragma unroll
    for (int j = 1; j < 8; j++) if (v[j] > lm) { lm = v[j]; lj = j; }

    const bool write_idx = (out_size >= 2 * Bb * TOPK);

    for (int t = 0; t < TOPK; t++) {
        // (val, col) for this thread's cached max
        float mv = lm;
        int   mi = (lj < 4) ? (c0 + lj) : (c1 + lj - 4);

        // warp reduce: prefer higher val, tie -> lower index
        #pragma unroll
        for (int off = 16; off > 0; off >>= 1) {
            float ov = __shfl_down_sync(0xFFFFFFFFu, mv, off);
            int   oi = __shfl_down_sync(0xFFFFFFFFu, mi, off);
            if (ov > mv || (ov == mv && oi < mi)) { mv = ov; mi = oi; }
        }
        if (lane == 0) { s_wv[wid] = mv; s_wi[wid] = mi; }
        __syncthreads();

        // cross-warp reduce (warp 0, 16 slots)
        if (wid == 0) {
            float rv2 = (lane < 16) ? s_wv[lane] : -INFINITY;
            int   ri2 = (lane < 16) ? s_wi[lane] : 0x7FFFFFFF;
            #pragma unroll
            for (int off = 8; off > 0; off >>= 1) {
                float ov = __shfl_down_sync(0xFFFFFFFFu, rv2, off);
                int   oi = __shfl_down_sync(0xFFFFFFFFu, ri2, off);
                if (ov > rv2 || (ov == rv2 && oi < ri2)) { rv2 = ov; ri2 = oi; }
            }
            if (lane == 0) {
                out[b * TOPK + t] = rv2;
                if (write_idx) out[Bb * TOPK + b * TOPK + t] = (float)ri2;
                s_bi = ri2;
            }
        }
        __syncthreads();

        // winner thread removes its element and recomputes its cached max
        const int win = s_bi;
        int j = -1;
        if (win >= c0 && win < c0 + 4)      j = win - c0;
        else if (win >= c1 && win < c1 + 4) j = 4 + (win - c1);
        if (j >= 0) {
            v[j] = -INFINITY;
            lm = v[0]; lj = 0;
            #pragma unroll
            for (int jj = 1; jj < 8; jj++) if (v[jj] > lm) { lm = v[jj]; lj = jj; }
        }
        __syncthreads();
    }
}

// ---------------------------------------------------------------------------
// Launch: inputs in metadata order: x, weight, bias, prev_idx, (top_k)
// ---------------------------------------------------------------------------
extern "C" void kernel_launch(void* const* d_in, const int* in_sizes, int n_in,
                              void* d_out, int out_size) {
    const float* x        = (const float*)d_in[0];
    const float* weight   = (const float*)d_in[1];
    const float* bias     = (const float*)d_in[2];
    const int*   prev_idx = (const int*)d_in[3];
    float* out = (float*)d_out;

    {
        dim3 grid(IN_ / 32, OUT_ / 32);
        dim3 block(32, 8);
        transpose_kernel<<<grid, block>>>(weight);
    }
    router_topk_kernel<<<Bb, 512>>>(x, prev_idx, bias, out, out_size);
}